// round 10
// baseline (speedup 1.0000x reference)
#include <cuda_runtime.h>
#include <cuda_bf16.h>

#define BATCH 8
#define SEQ   8192
#define DMODEL 1024
#define NTOK (BATCH * SEQ)
#define FULL 0xFFFFFFFFu

// Scratch: sortable keys per token. Active key = monotone uint transform of
// score (always >= 0x00800000 for finite scores); inactive = 0.
__device__ unsigned int g_keys[NTOK];

// ---------------------------------------------------------------------------
// Kernel 1: scores[b,s] = dot(hidden[b,s,:], w) + bias ; key = sortable(score)
// One warp per token; streams 256 MB of hidden once (HBM-bound, ~6.2 TB/s).
// ---------------------------------------------------------------------------
__global__ void __launch_bounds__(256)
score_kernel(const float* __restrict__ hidden,
             const unsigned int* __restrict__ mask,
             const float* __restrict__ w,
             const float* __restrict__ bias)
{
    int warp = (blockIdx.x * blockDim.x + threadIdx.x) >> 5;
    int lane = threadIdx.x & 31;
    if (warp >= NTOK) return;

    const float4* hp = reinterpret_cast<const float4*>(hidden + (size_t)warp * DMODEL);
    const float4* wp = reinterpret_cast<const float4*>(w);

    float acc = 0.0f;
#pragma unroll
    for (int i = 0; i < 8; i++) {
        float4 a = __ldcs(hp + lane + i * 32);   // streaming, evict-first
        float4 c = wp[lane + i * 32];            // hot in L1
        acc += a.x * c.x + a.y * c.y + a.z * c.z + a.w * c.w;
    }
#pragma unroll
    for (int o = 16; o; o >>= 1) acc += __shfl_xor_sync(FULL, acc, o);

    if (lane == 0) {
        float s = acc + bias[0];
        unsigned int u = __float_as_uint(s);
        u = (u & 0x80000000u) ? ~u : (u | 0x80000000u);  // order-preserving
        g_keys[warp] = (mask[warp] != 0u) ? u : 0u;      // inactive -> 0
    }
}

// ---------------------------------------------------------------------------
// Kernel 2: per-row exact variable top-k, stable lowest-index tie break.
// One block/row, 1024 threads, 8 contiguous keys/thread in registers.
// 3-pass radix select [13,11,8]: wide first pass (8192 bins) spreads the
// hot-bin ATOMS conflicts of N(0,1)-concentrated keys. In-place suffix scan,
// minimal syncs.
// ---------------------------------------------------------------------------
__device__ __forceinline__ int block_reduce_int(int v, int* red)
{
    int lane = threadIdx.x & 31, wid = threadIdx.x >> 5;
#pragma unroll
    for (int o = 16; o; o >>= 1) v += __shfl_xor_sync(FULL, v, o);
    if (lane == 0) red[wid] = v;
    __syncthreads();
    if (wid == 0) {
        int x = (lane < 32) ? red[lane] : 0;
#pragma unroll
        for (int o = 16; o; o >>= 1) x += __shfl_xor_sync(FULL, x, o);
        if (lane == 0) red[0] = x;
    }
    __syncthreads();
    int r = red[0];
    __syncthreads();
    return r;
}

// In-place suffix scan of hist[0..NB) (hist[NB] must be 0), then pick the
// boundary bin: hist_suffix[b] >= krem > hist_suffix[b+1].
// Writes {bin, krem - hist_suffix[b+1]} into bcast. Ends with __syncthreads.
template<int NB, int BPT>
__device__ __forceinline__ void suffix_pick(int* hist, int* wsum, int krem, int* bcast)
{
    const int tid = threadIdx.x, lane = tid & 31, wid = tid >> 5;
    const bool own = (tid * BPT) < NB;
    const int base = NB - 1 - tid * BPT;

    int local = 0;
    if (own) {
#pragma unroll
        for (int i = 0; i < BPT; i++) local += hist[base - i];
    }
    int s = local;
#pragma unroll
    for (int d = 1; d < 32; d <<= 1) {
        int n2 = __shfl_up_sync(FULL, s, d);
        if (lane >= d) s += n2;
    }
    if (lane == 31) wsum[wid] = s;
    __syncthreads();
    if (wid == 0) {
        int x = wsum[lane];
#pragma unroll
        for (int d = 1; d < 32; d <<= 1) {
            int n2 = __shfl_up_sync(FULL, x, d);
            if (lane >= d) x += n2;
        }
        wsum[lane] = x;
    }
    __syncthreads();
    if (own) {
        int run = s - local + ((wid > 0) ? wsum[wid - 1] : 0);  // exclusive
#pragma unroll
        for (int i = 0; i < BPT; i++) {
            int b = base - i;
            run += hist[b];
            hist[b] = run;          // overwrite with suffix sum
        }
    }
    __syncthreads();
    if (own) {
#pragma unroll
        for (int i = 0; i < BPT; i++) {
            int b = base - i;
            int S = hist[b], Sn = hist[b + 1];
            if (S >= krem && Sn < krem) {   // unique (suffix monotone)
                bcast[0] = b;
                bcast[1] = krem - Sn;
            }
        }
    }
    __syncthreads();
}

__global__ void __launch_bounds__(1024)
select_kernel(float* __restrict__ out)
{
    __shared__ int hist[8193];   // 32 KB + sentinel
    __shared__ int wsum[32];
    __shared__ int red[32];
    __shared__ int bcast[2];

    const int b = blockIdx.x, tid = threadIdx.x;
    const int lane = tid & 31, wid = tid >> 5;
    const unsigned int* keys = g_keys + b * SEQ;
    float* o = out + b * SEQ;

    // Contiguous ownership: indices [tid*8, tid*8+8)
    const uint4 k0 = __ldcg(reinterpret_cast<const uint4*>(keys) + tid * 2);
    const uint4 k1 = __ldcg(reinterpret_cast<const uint4*>(keys) + tid * 2 + 1);
    unsigned int v[8] = {k0.x, k0.y, k0.z, k0.w, k1.x, k1.y, k1.z, k1.w};

    // ---- Pass 1 zero (interleaved with na reduce) ----
#pragma unroll
    for (int j = 0; j < 8; j++) hist[tid + j * 1024] = 0;
    if (tid == 0) hist[8192] = 0;

    int na = 0;
#pragma unroll
    for (int i = 0; i < 8; i++) na += (v[i] != 0u);
    const int n_active = block_reduce_int(na, red);   // also orders hist zeroing

    if (n_active == 0) {
        float4 z = make_float4(0.f, 0.f, 0.f, 0.f);
        reinterpret_cast<float4*>(o)[tid * 2]     = z;
        reinterpret_cast<float4*>(o)[tid * 2 + 1] = z;
        return;
    }
    const int k = (n_active + 1) >> 1;   // max(1, ceil(n/2)), n >= 1

    unsigned int prefix;
    int krem;

    // ---- Pass 1: bits [31:19], 8192 bins, all keys ----
#pragma unroll
    for (int i = 0; i < 8; i++)
        atomicAdd(&hist[v[i] >> 19], 1);
    __syncthreads();
    suffix_pick<8192, 8>(hist, wsum, k, bcast);
    prefix = ((unsigned int)bcast[0]) << 19;
    krem = bcast[1];

    // ---- Pass 2: bits [18:8], 2048 bins, prefix-matching keys ----
    if (tid < 1024) { hist[tid] = 0; hist[tid + 1024] = 0; }
    if (tid == 0) hist[2048] = 0;
    __syncthreads();
#pragma unroll
    for (int i = 0; i < 8; i++)
        if ((v[i] & 0xFFF80000u) == prefix)
            atomicAdd(&hist[(v[i] >> 8) & 2047u], 1);
    __syncthreads();
    suffix_pick<2048, 2>(hist, wsum, krem, bcast);
    prefix |= ((unsigned int)bcast[0]) << 8;
    krem = bcast[1];

    // ---- Pass 3: bits [7:0], 256 bins ----
    if (tid < 257) hist[tid] = 0;
    __syncthreads();
#pragma unroll
    for (int i = 0; i < 8; i++)
        if ((v[i] & 0xFFFFFF00u) == prefix)
            atomicAdd(&hist[v[i] & 255u], 1);
    __syncthreads();
    suffix_pick<256, 1>(hist, wsum, krem, bcast);
    const unsigned int t = prefix | (unsigned int)bcast[0];

    // ---- strictly-greater count -> number of equals to admit ----
    int cgt = 0;
#pragma unroll
    for (int i = 0; i < 8; i++) cgt += (v[i] > t);
    const int count_gt = block_reduce_int(cgt, red);
    const int mneed = k - count_gt;   // >= 1

    // ---- stable rank among equals: exclusive block scan (thread order ==
    //      index order thanks to contiguous ownership) ----
    int le = 0;
#pragma unroll
    for (int i = 0; i < 8; i++) le += (v[i] == t);
    int s = le;
#pragma unroll
    for (int d = 1; d < 32; d <<= 1) {
        int n2 = __shfl_up_sync(FULL, s, d);
        if (lane >= d) s += n2;
    }
    if (lane == 31) wsum[wid] = s;
    __syncthreads();
    if (wid == 0) {
        int x = wsum[lane];
#pragma unroll
        for (int d = 1; d < 32; d <<= 1) {
            int n2 = __shfl_up_sync(FULL, x, d);
            if (lane >= d) x += n2;
        }
        wsum[lane] = x;
    }
    __syncthreads();
    int eq_rank = s - le + ((wid > 0) ? wsum[wid - 1] : 0);

    // ---- emit keep mask as float 1.0/0.0 ----
    float r8[8];
#pragma unroll
    for (int i = 0; i < 8; i++) {
        bool keep;
        if (v[i] > t)       keep = true;
        else if (v[i] == t) { keep = (eq_rank < mneed); eq_rank++; }
        else                keep = false;
        r8[i] = keep ? 1.0f : 0.0f;
    }
    reinterpret_cast<float4*>(o)[tid * 2]     = make_float4(r8[0], r8[1], r8[2], r8[3]);
    reinterpret_cast<float4*>(o)[tid * 2 + 1] = make_float4(r8[4], r8[5], r8[6], r8[7]);
}

extern "C" void kernel_launch(void* const* d_in, const int* in_sizes, int n_in,
                              void* d_out, int out_size)
{
    // Bind inputs by element count (all distinct):
    //   hidden 67108864, mask 65536, w 1024, bias 1
    const float*        hidden = nullptr;
    const unsigned int* mask   = nullptr;
    const float*        w      = nullptr;
    const float*        bias   = nullptr;
    for (int i = 0; i < n_in; i++) {
        if      (in_sizes[i] == 67108864) hidden = (const float*)d_in[i];
        else if (in_sizes[i] == 65536)    mask   = (const unsigned int*)d_in[i];
        else if (in_sizes[i] == 1024)     w      = (const float*)d_in[i];
        else if (in_sizes[i] == 1)        bias   = (const float*)d_in[i];
    }
    float* out = (float*)d_out;

    score_kernel<<<NTOK / 8, 256>>>(hidden, mask, w, bias);
    select_kernel<<<BATCH, 1024>>>(out);
}